// round 14
// baseline (speedup 1.0000x reference)
#include <cuda_runtime.h>
#include <cuda_bf16.h>

#define BATCH 8192
#define DIM   64

static constexpr float TEMP   = 0.07f;
static constexpr float LOG2E  = 1.4426950408889634f;
// exp(dot/T) == exp2(dot * LOG2E / T)
static constexpr float ESCALE = LOG2E / TEMP;

__device__ float g_img[BATCH * DIM];   // normalized image features
__device__ float g_txt[BATCH * DIM];   // normalized text features
__device__ float g_diag[BATCH];        // diag logits (already / T)
__device__ float g_row[BATCH];         // sum_j exp(l_ij)
__device__ float g_col[BATCH];         // sum_i exp(l_ij)

// ---------------------------------------------------------------------------
// packed f32x2 helpers (sm_100+)
// ---------------------------------------------------------------------------
__device__ __forceinline__ unsigned long long fma2(unsigned long long a,
                                                   unsigned long long b,
                                                   unsigned long long c) {
    unsigned long long d;
    asm("fma.rn.f32x2 %0, %1, %2, %3;" : "=l"(d) : "l"(a), "l"(b), "l"(c));
    return d;
}
__device__ __forceinline__ unsigned long long bcast2(float x) {
    unsigned long long d;
    unsigned u = __float_as_uint(x);
    asm("mov.b64 %0, {%1, %1};" : "=l"(d) : "r"(u));
    return d;
}
__device__ __forceinline__ float lo32(unsigned long long u) {
    return __uint_as_float((unsigned)(u & 0xffffffffull));
}
__device__ __forceinline__ float hi32(unsigned long long u) {
    return __uint_as_float((unsigned)(u >> 32));
}

// ---------------------------------------------------------------------------
// Phase 1: normalize both feature sets, compute diagonal logits, zero sums.
// 1 warp per row; 1024 blocks x 256 threads.
// ---------------------------------------------------------------------------
__global__ void prep_kernel(const float* __restrict__ img,
                            const float* __restrict__ txt) {
    int tid = threadIdx.x;
    int gt  = blockIdx.x * 256 + tid;
    if (gt < BATCH) { g_row[gt] = 0.0f; g_col[gt] = 0.0f; }

    int warp = tid >> 5;
    int lane = tid & 31;
    int row  = blockIdx.x * 8 + warp;

    float2 xi = ((const float2*)(img + row * DIM))[lane];
    float2 xt = ((const float2*)(txt + row * DIM))[lane];

    float ssi = xi.x * xi.x + xi.y * xi.y;
    float sst = xt.x * xt.x + xt.y * xt.y;
    float cr  = xi.x * xt.x + xi.y * xt.y;
#pragma unroll
    for (int m = 16; m > 0; m >>= 1) {
        ssi += __shfl_xor_sync(0xffffffffu, ssi, m);
        sst += __shfl_xor_sync(0xffffffffu, sst, m);
        cr  += __shfl_xor_sync(0xffffffffu, cr,  m);
    }
    float invi = 1.0f / fmaxf(sqrtf(ssi), 1e-12f);
    float invt = 1.0f / fmaxf(sqrtf(sst), 1e-12f);

    ((float2*)(g_img + row * DIM))[lane] = make_float2(xi.x * invi, xi.y * invi);
    ((float2*)(g_txt + row * DIM))[lane] = make_float2(xt.x * invt, xt.y * invt);
    if (lane == 0) g_diag[row] = cr * invi * invt * (1.0f / TEMP);
}

// ---------------------------------------------------------------------------
// Phase 2: 128x128 tile of exp(logits); accumulate row/col sums.
// 256 threads; thread = 8 rows x 8 cols; rows packed in pairs for f32x2.
// Dynamic smem: As[64][128] + Bs[64][128] = 64 KB (k-major).
// ---------------------------------------------------------------------------
__global__ __launch_bounds__(256, 2) void tile_kernel() {
    extern __shared__ float smem[];
    float (*As)[128] = (float(*)[128])smem;                 // As[k][m]
    float (*Bs)[128] = (float(*)[128])(smem + 64 * 128);    // Bs[k][n]

    int tid = threadIdx.x;
    int i0  = blockIdx.y * 128;
    int j0  = blockIdx.x * 128;

    // ---- load tiles, transposing to k-major ----
    {
        int r  = tid >> 1;            // row within tile: 0..127
        int kq = (tid & 1) * 8;       // float4 index: 0 or 8
        const float4* arow = (const float4*)(g_img + (size_t)(i0 + r) * DIM);
        const float4* brow = (const float4*)(g_txt + (size_t)(j0 + r) * DIM);
#pragma unroll
        for (int q = 0; q < 8; q++) {
            float4 v = arow[kq + q];
            float4 w = brow[kq + q];
            int k = (kq + q) * 4;
            As[k + 0][r] = v.x; As[k + 1][r] = v.y;
            As[k + 2][r] = v.z; As[k + 3][r] = v.w;
            Bs[k + 0][r] = w.x; Bs[k + 1][r] = w.y;
            Bs[k + 2][r] = w.z; Bs[k + 3][r] = w.w;
        }
    }
    __syncthreads();

    int tx = tid & 15;          // col group
    int ty = tid >> 4;          // row group
    int rbase = ty * 8;
    int cbase = tx * 8;

    // acc[mp][n]: lo lane = row rbase+2mp, hi lane = row rbase+2mp+1, col cbase+n
    unsigned long long acc[4][8];
#pragma unroll
    for (int a = 0; a < 4; a++)
#pragma unroll
        for (int b = 0; b < 8; b++) acc[a][b] = 0ull;

#pragma unroll 4
    for (int k = 0; k < 64; k++) {
        const ulonglong2* ap = (const ulonglong2*)&As[k][rbase];
        ulonglong2 aa = ap[0];
        ulonglong2 ab = ap[1];
        unsigned long long a2[4] = {aa.x, aa.y, ab.x, ab.y};

        const float4* bp = (const float4*)&Bs[k][cbase];
        float4 b0 = bp[0], b1 = bp[1];
        unsigned long long b2[8];
        b2[0] = bcast2(b0.x); b2[1] = bcast2(b0.y);
        b2[2] = bcast2(b0.z); b2[3] = bcast2(b0.w);
        b2[4] = bcast2(b1.x); b2[5] = bcast2(b1.y);
        b2[6] = bcast2(b1.z); b2[7] = bcast2(b1.w);

#pragma unroll
        for (int mp = 0; mp < 4; mp++)
#pragma unroll
            for (int n = 0; n < 8; n++)
                acc[mp][n] = fma2(a2[mp], b2[n], acc[mp][n]);
    }

    // ---- exponentiate + per-thread partial sums ----
    float rsum[8], csum[8];
#pragma unroll
    for (int r = 0; r < 8; r++) { rsum[r] = 0.0f; csum[r] = 0.0f; }

#pragma unroll
    for (int mp = 0; mp < 4; mp++) {
#pragma unroll
        for (int n = 0; n < 8; n++) {
            float e0 = exp2f(lo32(acc[mp][n]) * ESCALE);
            float e1 = exp2f(hi32(acc[mp][n]) * ESCALE);
            rsum[2 * mp]     += e0;
            rsum[2 * mp + 1] += e1;
            csum[n]          += e0 + e1;
        }
    }

    // ---- row sums: shfl-reduce across the 16 col-groups in each half-warp ----
#pragma unroll
    for (int m = 1; m < 16; m <<= 1)
#pragma unroll
        for (int r = 0; r < 8; r++)
            rsum[r] += __shfl_xor_sync(0xffffffffu, rsum[r], m);
    if (tx == 0) {
#pragma unroll
        for (int r = 0; r < 8; r++)
            atomicAdd(&g_row[i0 + rbase + r], rsum[r]);
    }

    // ---- col sums: fold the two half-warps (same tx), then smem reduce ----
#pragma unroll
    for (int n = 0; n < 8; n++)
        csum[n] += __shfl_xor_sync(0xffffffffu, csum[n], 16);

    __syncthreads();                 // done reading As; reuse as col buffer
    float* colbuf = &As[0][0];
    if (tid < 128) colbuf[tid] = 0.0f;
    __syncthreads();
    if ((tid & 16) == 0) {           // one half-warp per warp contributes
#pragma unroll
        for (int n = 0; n < 8; n++)
            atomicAdd(&colbuf[cbase + n], csum[n]);
    }
    __syncthreads();
    if (tid < 128) atomicAdd(&g_col[j0 + tid], colbuf[tid]);
}

// ---------------------------------------------------------------------------
// Phase 3: focal-loss reduction (double accumulation for the 8192-term sum).
// ---------------------------------------------------------------------------
__global__ void final_kernel(float* __restrict__ out) {
    __shared__ double red[256];
    int tid = threadIdx.x;
    double acc = 0.0;
    for (int i = tid; i < BATCH; i += 256) {
        float d  = g_diag[i];
        float lr = d - logf(g_row[i]);   // diag log-softmax over rows (i2t)
        float lc = d - logf(g_col[i]);   // diag log-softmax over cols (t2i)
        float p  = expf(lr);             // row-softmax positive prob
        float om = 1.0f - p;
        float w  = om * om;              // ALPHA=1, GAMMA=2
        acc += (double)(w * (-(lr + lc)));
    }
    red[tid] = acc;
    __syncthreads();
#pragma unroll
    for (int s = 128; s > 0; s >>= 1) {
        if (tid < s) red[tid] += red[tid + s];
        __syncthreads();
    }
    if (tid == 0) out[0] = (float)(red[0] / (2.0 * (double)BATCH));
}

// ---------------------------------------------------------------------------
extern "C" void kernel_launch(void* const* d_in, const int* in_sizes, int n_in,
                              void* d_out, int out_size) {
    const float* img = (const float*)d_in[0];
    const float* txt = (const float*)d_in[1];
    float* out = (float*)d_out;

    static bool attr_done = false;
    if (!attr_done) {
        cudaFuncSetAttribute(tile_kernel,
                             cudaFuncAttributeMaxDynamicSharedMemorySize,
                             64 * 1024);
        attr_done = true;
    }

    prep_kernel<<<BATCH / 8, 256>>>(img, txt);
    dim3 grid(BATCH / 128, BATCH / 128);
    tile_kernel<<<grid, 256, 64 * 1024>>>();
    final_kernel<<<1, 256>>>(out);
}

// round 15
// speedup vs baseline: 1.0010x; 1.0010x over previous
#include <cuda_runtime.h>
#include <cuda_bf16.h>

#define BATCH 8192
#define DIM   64

static constexpr float TEMP   = 0.07f;
static constexpr float LOG2E  = 1.4426950408889634f;
// exp(dot/T) == exp2(dot * LOG2E / T)
static constexpr float ESCALE = LOG2E / TEMP;

__device__ float g_img[BATCH * DIM];   // normalized image features
__device__ float g_txt[BATCH * DIM];   // normalized text features
__device__ float g_diag[BATCH];        // diag logits (already / T)
__device__ float g_row[BATCH];         // sum_j exp(l_ij)
__device__ float g_col[BATCH];         // sum_i exp(l_ij)

// ---------------------------------------------------------------------------
// packed f32x2 helpers (sm_100+)
// ---------------------------------------------------------------------------
__device__ __forceinline__ unsigned long long fma2(unsigned long long a,
                                                   unsigned long long b,
                                                   unsigned long long c) {
    unsigned long long d;
    asm("fma.rn.f32x2 %0, %1, %2, %3;" : "=l"(d) : "l"(a), "l"(b), "l"(c));
    return d;
}
__device__ __forceinline__ unsigned long long bcast2(float x) {
    unsigned long long d;
    unsigned u = __float_as_uint(x);
    asm("mov.b64 %0, {%1, %1};" : "=l"(d) : "r"(u));
    return d;
}
__device__ __forceinline__ float lo32(unsigned long long u) {
    return __uint_as_float((unsigned)(u & 0xffffffffull));
}
__device__ __forceinline__ float hi32(unsigned long long u) {
    return __uint_as_float((unsigned)(u >> 32));
}

// ---------------------------------------------------------------------------
// Phase 1: normalize both feature sets, compute diagonal logits, zero sums.
// 1 warp per row; 1024 blocks x 256 threads.
// ---------------------------------------------------------------------------
__global__ void prep_kernel(const float* __restrict__ img,
                            const float* __restrict__ txt) {
    int tid = threadIdx.x;
    int gt  = blockIdx.x * 256 + tid;
    if (gt < BATCH) { g_row[gt] = 0.0f; g_col[gt] = 0.0f; }

    int warp = tid >> 5;
    int lane = tid & 31;
    int row  = blockIdx.x * 8 + warp;

    float2 xi = ((const float2*)(img + row * DIM))[lane];
    float2 xt = ((const float2*)(txt + row * DIM))[lane];

    float ssi = xi.x * xi.x + xi.y * xi.y;
    float sst = xt.x * xt.x + xt.y * xt.y;
    float cr  = xi.x * xt.x + xi.y * xt.y;
#pragma unroll
    for (int m = 16; m > 0; m >>= 1) {
        ssi += __shfl_xor_sync(0xffffffffu, ssi, m);
        sst += __shfl_xor_sync(0xffffffffu, sst, m);
        cr  += __shfl_xor_sync(0xffffffffu, cr,  m);
    }
    float invi = 1.0f / fmaxf(sqrtf(ssi), 1e-12f);
    float invt = 1.0f / fmaxf(sqrtf(sst), 1e-12f);

    ((float2*)(g_img + row * DIM))[lane] = make_float2(xi.x * invi, xi.y * invi);
    ((float2*)(g_txt + row * DIM))[lane] = make_float2(xt.x * invt, xt.y * invt);
    if (lane == 0) g_diag[row] = cr * invi * invt * (1.0f / TEMP);
}

// ---------------------------------------------------------------------------
// Phase 2: 128x128 tile of exp(logits); accumulate row/col sums.
// 256 threads; thread = 8 rows x 8 cols; rows packed in pairs for f32x2.
// Dynamic smem: As[64][128] + Bs[64][128] = 64 KB (k-major).
// ---------------------------------------------------------------------------
__global__ __launch_bounds__(256, 2) void tile_kernel() {
    extern __shared__ float smem[];
    float (*As)[128] = (float(*)[128])smem;                 // As[k][m]
    float (*Bs)[128] = (float(*)[128])(smem + 64 * 128);    // Bs[k][n]

    int tid = threadIdx.x;
    int i0  = blockIdx.y * 128;
    int j0  = blockIdx.x * 128;

    // ---- load tiles, transposing to k-major ----
    {
        int r  = tid >> 1;            // row within tile: 0..127
        int kq = (tid & 1) * 8;       // float4 index: 0 or 8
        const float4* arow = (const float4*)(g_img + (size_t)(i0 + r) * DIM);
        const float4* brow = (const float4*)(g_txt + (size_t)(j0 + r) * DIM);
#pragma unroll
        for (int q = 0; q < 8; q++) {
            float4 v = arow[kq + q];
            float4 w = brow[kq + q];
            int k = (kq + q) * 4;
            As[k + 0][r] = v.x; As[k + 1][r] = v.y;
            As[k + 2][r] = v.z; As[k + 3][r] = v.w;
            Bs[k + 0][r] = w.x; Bs[k + 1][r] = w.y;
            Bs[k + 2][r] = w.z; Bs[k + 3][r] = w.w;
        }
    }
    __syncthreads();

    int tx = tid & 15;          // col group
    int ty = tid >> 4;          // row group
    int rbase = ty * 8;
    int cbase = tx * 8;

    // acc[mp][n]: lo lane = row rbase+2mp, hi lane = row rbase+2mp+1, col cbase+n
    unsigned long long acc[4][8];
#pragma unroll
    for (int a = 0; a < 4; a++)
#pragma unroll
        for (int b = 0; b < 8; b++) acc[a][b] = 0ull;

#pragma unroll 4
    for (int k = 0; k < 64; k++) {
        const ulonglong2* ap = (const ulonglong2*)&As[k][rbase];
        ulonglong2 aa = ap[0];
        ulonglong2 ab = ap[1];
        unsigned long long a2[4] = {aa.x, aa.y, ab.x, ab.y};

        const float4* bp = (const float4*)&Bs[k][cbase];
        float4 b0 = bp[0], b1 = bp[1];
        unsigned long long b2[8];
        b2[0] = bcast2(b0.x); b2[1] = bcast2(b0.y);
        b2[2] = bcast2(b0.z); b2[3] = bcast2(b0.w);
        b2[4] = bcast2(b1.x); b2[5] = bcast2(b1.y);
        b2[6] = bcast2(b1.z); b2[7] = bcast2(b1.w);

#pragma unroll
        for (int mp = 0; mp < 4; mp++)
#pragma unroll
            for (int n = 0; n < 8; n++)
                acc[mp][n] = fma2(a2[mp], b2[n], acc[mp][n]);
    }

    // ---- exponentiate + per-thread partial sums ----
    float rsum[8], csum[8];
#pragma unroll
    for (int r = 0; r < 8; r++) { rsum[r] = 0.0f; csum[r] = 0.0f; }

#pragma unroll
    for (int mp = 0; mp < 4; mp++) {
#pragma unroll
        for (int n = 0; n < 8; n++) {
            float e0 = exp2f(lo32(acc[mp][n]) * ESCALE);
            float e1 = exp2f(hi32(acc[mp][n]) * ESCALE);
            rsum[2 * mp]     += e0;
            rsum[2 * mp + 1] += e1;
            csum[n]          += e0 + e1;
        }
    }

    // ---- row sums: shfl-reduce across the 16 col-groups in each half-warp ----
#pragma unroll
    for (int m = 1; m < 16; m <<= 1)
#pragma unroll
        for (int r = 0; r < 8; r++)
            rsum[r] += __shfl_xor_sync(0xffffffffu, rsum[r], m);
    if (tx == 0) {
#pragma unroll
        for (int r = 0; r < 8; r++)
            atomicAdd(&g_row[i0 + rbase + r], rsum[r]);
    }

    // ---- col sums: fold the two half-warps (same tx), then smem reduce ----
#pragma unroll
    for (int n = 0; n < 8; n++)
        csum[n] += __shfl_xor_sync(0xffffffffu, csum[n], 16);

    __syncthreads();                 // done reading As; reuse as col buffer
    float* colbuf = &As[0][0];
    if (tid < 128) colbuf[tid] = 0.0f;
    __syncthreads();
    if ((tid & 16) == 0) {           // one half-warp per warp contributes
#pragma unroll
        for (int n = 0; n < 8; n++)
            atomicAdd(&colbuf[cbase + n], csum[n]);
    }
    __syncthreads();
    if (tid < 128) atomicAdd(&g_col[j0 + tid], colbuf[tid]);
}

// ---------------------------------------------------------------------------
// Phase 3: focal-loss reduction (double accumulation for the 8192-term sum).
// ---------------------------------------------------------------------------
__global__ void final_kernel(float* __restrict__ out) {
    __shared__ double red[256];
    int tid = threadIdx.x;
    double acc = 0.0;
    for (int i = tid; i < BATCH; i += 256) {
        float d  = g_diag[i];
        float lr = d - logf(g_row[i]);   // diag log-softmax over rows (i2t)
        float lc = d - logf(g_col[i]);   // diag log-softmax over cols (t2i)
        float p  = expf(lr);             // row-softmax positive prob
        float om = 1.0f - p;
        float w  = om * om;              // ALPHA=1, GAMMA=2
        acc += (double)(w * (-(lr + lc)));
    }
    red[tid] = acc;
    __syncthreads();
#pragma unroll
    for (int s = 128; s > 0; s >>= 1) {
        if (tid < s) red[tid] += red[tid + s];
        __syncthreads();
    }
    if (tid == 0) out[0] = (float)(red[0] / (2.0 * (double)BATCH));
}

// ---------------------------------------------------------------------------
extern "C" void kernel_launch(void* const* d_in, const int* in_sizes, int n_in,
                              void* d_out, int out_size) {
    const float* img = (const float*)d_in[0];
    const float* txt = (const float*)d_in[1];
    float* out = (float*)d_out;

    static bool attr_done = false;
    if (!attr_done) {
        cudaFuncSetAttribute(tile_kernel,
                             cudaFuncAttributeMaxDynamicSharedMemorySize,
                             64 * 1024);
        attr_done = true;
    }

    prep_kernel<<<BATCH / 8, 256>>>(img, txt);
    dim3 grid(BATCH / 128, BATCH / 128);
    tile_kernel<<<grid, 256, 64 * 1024>>>();
    final_kernel<<<1, 256>>>(out);
}

// round 16
// speedup vs baseline: 1.0033x; 1.0023x over previous
#include <cuda_runtime.h>
#include <cuda_bf16.h>

#define BATCH 8192
#define DIM   64

static constexpr float TEMP   = 0.07f;
static constexpr float LOG2E  = 1.4426950408889634f;
// exp(dot/T) == exp2(dot * LOG2E / T)
static constexpr float ESCALE = LOG2E / TEMP;

__device__ float g_img[BATCH * DIM];   // normalized image features
__device__ float g_txt[BATCH * DIM];   // normalized text features
__device__ float g_diag[BATCH];        // diag logits (already / T)
__device__ float g_row[BATCH];         // sum_j exp(l_ij)
__device__ float g_col[BATCH];         // sum_i exp(l_ij)

// ---------------------------------------------------------------------------
// packed f32x2 helpers (sm_100+)
// ---------------------------------------------------------------------------
__device__ __forceinline__ unsigned long long fma2(unsigned long long a,
                                                   unsigned long long b,
                                                   unsigned long long c) {
    unsigned long long d;
    asm("fma.rn.f32x2 %0, %1, %2, %3;" : "=l"(d) : "l"(a), "l"(b), "l"(c));
    return d;
}
__device__ __forceinline__ unsigned long long bcast2(float x) {
    unsigned long long d;
    unsigned u = __float_as_uint(x);
    asm("mov.b64 %0, {%1, %1};" : "=l"(d) : "r"(u));
    return d;
}
__device__ __forceinline__ float lo32(unsigned long long u) {
    return __uint_as_float((unsigned)(u & 0xffffffffull));
}
__device__ __forceinline__ float hi32(unsigned long long u) {
    return __uint_as_float((unsigned)(u >> 32));
}

// ---------------------------------------------------------------------------
// Phase 1: normalize both feature sets, compute diagonal logits, zero sums.
// 1 warp per row; 1024 blocks x 256 threads.
// ---------------------------------------------------------------------------
__global__ void prep_kernel(const float* __restrict__ img,
                            const float* __restrict__ txt) {
    int tid = threadIdx.x;
    int gt  = blockIdx.x * 256 + tid;
    if (gt < BATCH) { g_row[gt] = 0.0f; g_col[gt] = 0.0f; }

    int warp = tid >> 5;
    int lane = tid & 31;
    int row  = blockIdx.x * 8 + warp;

    float2 xi = ((const float2*)(img + row * DIM))[lane];
    float2 xt = ((const float2*)(txt + row * DIM))[lane];

    float ssi = xi.x * xi.x + xi.y * xi.y;
    float sst = xt.x * xt.x + xt.y * xt.y;
    float cr  = xi.x * xt.x + xi.y * xt.y;
#pragma unroll
    for (int m = 16; m > 0; m >>= 1) {
        ssi += __shfl_xor_sync(0xffffffffu, ssi, m);
        sst += __shfl_xor_sync(0xffffffffu, sst, m);
        cr  += __shfl_xor_sync(0xffffffffu, cr,  m);
    }
    float invi = 1.0f / fmaxf(sqrtf(ssi), 1e-12f);
    float invt = 1.0f / fmaxf(sqrtf(sst), 1e-12f);

    ((float2*)(g_img + row * DIM))[lane] = make_float2(xi.x * invi, xi.y * invi);
    ((float2*)(g_txt + row * DIM))[lane] = make_float2(xt.x * invt, xt.y * invt);
    if (lane == 0) g_diag[row] = cr * invi * invt * (1.0f / TEMP);
}

// ---------------------------------------------------------------------------
// Phase 2: 128x128 tile of exp(logits); accumulate row/col sums.
// 256 threads; thread = 8 rows x 8 cols; rows packed in pairs for f32x2.
// Dynamic smem: As[64][128] + Bs[64][128] = 64 KB (k-major).
// ---------------------------------------------------------------------------
__global__ __launch_bounds__(256, 2) void tile_kernel() {
    extern __shared__ float smem[];
    float (*As)[128] = (float(*)[128])smem;                 // As[k][m]
    float (*Bs)[128] = (float(*)[128])(smem + 64 * 128);    // Bs[k][n]

    int tid = threadIdx.x;
    int i0  = blockIdx.y * 128;
    int j0  = blockIdx.x * 128;

    // ---- load tiles, transposing to k-major ----
    {
        int r  = tid >> 1;            // row within tile: 0..127
        int kq = (tid & 1) * 8;       // float4 index: 0 or 8
        const float4* arow = (const float4*)(g_img + (size_t)(i0 + r) * DIM);
        const float4* brow = (const float4*)(g_txt + (size_t)(j0 + r) * DIM);
#pragma unroll
        for (int q = 0; q < 8; q++) {
            float4 v = arow[kq + q];
            float4 w = brow[kq + q];
            int k = (kq + q) * 4;
            As[k + 0][r] = v.x; As[k + 1][r] = v.y;
            As[k + 2][r] = v.z; As[k + 3][r] = v.w;
            Bs[k + 0][r] = w.x; Bs[k + 1][r] = w.y;
            Bs[k + 2][r] = w.z; Bs[k + 3][r] = w.w;
        }
    }
    __syncthreads();

    int tx = tid & 15;          // col group
    int ty = tid >> 4;          // row group
    int rbase = ty * 8;
    int cbase = tx * 8;

    // acc[mp][n]: lo lane = row rbase+2mp, hi lane = row rbase+2mp+1, col cbase+n
    unsigned long long acc[4][8];
#pragma unroll
    for (int a = 0; a < 4; a++)
#pragma unroll
        for (int b = 0; b < 8; b++) acc[a][b] = 0ull;

#pragma unroll 4
    for (int k = 0; k < 64; k++) {
        const ulonglong2* ap = (const ulonglong2*)&As[k][rbase];
        ulonglong2 aa = ap[0];
        ulonglong2 ab = ap[1];
        unsigned long long a2[4] = {aa.x, aa.y, ab.x, ab.y};

        const float4* bp = (const float4*)&Bs[k][cbase];
        float4 b0 = bp[0], b1 = bp[1];
        unsigned long long b2[8];
        b2[0] = bcast2(b0.x); b2[1] = bcast2(b0.y);
        b2[2] = bcast2(b0.z); b2[3] = bcast2(b0.w);
        b2[4] = bcast2(b1.x); b2[5] = bcast2(b1.y);
        b2[6] = bcast2(b1.z); b2[7] = bcast2(b1.w);

#pragma unroll
        for (int mp = 0; mp < 4; mp++)
#pragma unroll
            for (int n = 0; n < 8; n++)
                acc[mp][n] = fma2(a2[mp], b2[n], acc[mp][n]);
    }

    // ---- exponentiate + per-thread partial sums ----
    float rsum[8], csum[8];
#pragma unroll
    for (int r = 0; r < 8; r++) { rsum[r] = 0.0f; csum[r] = 0.0f; }

#pragma unroll
    for (int mp = 0; mp < 4; mp++) {
#pragma unroll
        for (int n = 0; n < 8; n++) {
            float e0 = exp2f(lo32(acc[mp][n]) * ESCALE);
            float e1 = exp2f(hi32(acc[mp][n]) * ESCALE);
            rsum[2 * mp]     += e0;
            rsum[2 * mp + 1] += e1;
            csum[n]          += e0 + e1;
        }
    }

    // ---- row sums: shfl-reduce across the 16 col-groups in each half-warp ----
#pragma unroll
    for (int m = 1; m < 16; m <<= 1)
#pragma unroll
        for (int r = 0; r < 8; r++)
            rsum[r] += __shfl_xor_sync(0xffffffffu, rsum[r], m);
    if (tx == 0) {
#pragma unroll
        for (int r = 0; r < 8; r++)
            atomicAdd(&g_row[i0 + rbase + r], rsum[r]);
    }

    // ---- col sums: fold the two half-warps (same tx), then smem reduce ----
#pragma unroll
    for (int n = 0; n < 8; n++)
        csum[n] += __shfl_xor_sync(0xffffffffu, csum[n], 16);

    __syncthreads();                 // done reading As; reuse as col buffer
    float* colbuf = &As[0][0];
    if (tid < 128) colbuf[tid] = 0.0f;
    __syncthreads();
    if ((tid & 16) == 0) {           // one half-warp per warp contributes
#pragma unroll
        for (int n = 0; n < 8; n++)
            atomicAdd(&colbuf[cbase + n], csum[n]);
    }
    __syncthreads();
    if (tid < 128) atomicAdd(&g_col[j0 + tid], colbuf[tid]);
}

// ---------------------------------------------------------------------------
// Phase 3: focal-loss reduction (double accumulation for the 8192-term sum).
// ---------------------------------------------------------------------------
__global__ void final_kernel(float* __restrict__ out) {
    __shared__ double red[256];
    int tid = threadIdx.x;
    double acc = 0.0;
    for (int i = tid; i < BATCH; i += 256) {
        float d  = g_diag[i];
        float lr = d - logf(g_row[i]);   // diag log-softmax over rows (i2t)
        float lc = d - logf(g_col[i]);   // diag log-softmax over cols (t2i)
        float p  = expf(lr);             // row-softmax positive prob
        float om = 1.0f - p;
        float w  = om * om;              // ALPHA=1, GAMMA=2
        acc += (double)(w * (-(lr + lc)));
    }
    red[tid] = acc;
    __syncthreads();
#pragma unroll
    for (int s = 128; s > 0; s >>= 1) {
        if (tid < s) red[tid] += red[tid + s];
        __syncthreads();
    }
    if (tid == 0) out[0] = (float)(red[0] / (2.0 * (double)BATCH));
}

// ---------------------------------------------------------------------------
extern "C" void kernel_launch(void* const* d_in, const int* in_sizes, int n_in,
                              void* d_out, int out_size) {
    const float* img = (const float*)d_in[0];
    const float* txt = (const float*)d_in[1];
    float* out = (float*)d_out;

    static bool attr_done = false;
    if (!attr_done) {
        cudaFuncSetAttribute(tile_kernel,
                             cudaFuncAttributeMaxDynamicSharedMemorySize,
                             64 * 1024);
        attr_done = true;
    }

    prep_kernel<<<BATCH / 8, 256>>>(img, txt);
    dim3 grid(BATCH / 128, BATCH / 128);
    tile_kernel<<<grid, 256, 64 * 1024>>>();
    final_kernel<<<1, 256>>>(out);
}